// round 1
// baseline (speedup 1.0000x reference)
#include <cuda_runtime.h>
#include <cuda_bf16.h>

// Synapse_66400194396810: out[m,n] = tanh( w2 . tanh( w1 @ (A[m,n], pre[n], post[m]) + b1 ) + b2 )
// M = N = 4096, Nh = 8. Elementwise MLP; MUFU(tanh)-bound by model (~40us floor), HBM floor ~16us.

#define NH 8

__device__ __forceinline__ float htanh(float x) {
    float y;
    asm("tanh.approx.f32 %0, %1;" : "=f"(y) : "f"(x));
    return y;
}
__device__ __forceinline__ float ex2f(float x) {
    float y;
    asm("ex2.approx.f32 %0, %1;" : "=f"(y) : "f"(x));
    return y;
}
__device__ __forceinline__ float rcpf(float x) {
    float y;
    asm("rcp.approx.f32 %0, %1;" : "=f"(y) : "f"(x));
    return y;
}

// Accurate final tanh: (e^{2x}-1)/(e^{2x}+1) via ex2; ~1e-6 rel err, no overflow (clamped).
__device__ __forceinline__ float tanh_acc(float x) {
    x = fminf(fmaxf(x, -9.01f), 9.01f);
    float e = ex2f(x * 2.8853900817779268f);  // 2*log2(e)
    return (e - 1.0f) * rcpf(e + 1.0f);
}

__global__ void __launch_bounds__(256) synapse_kernel(
    const float* __restrict__ A,
    const float* __restrict__ pre,
    const float* __restrict__ post,
    const float* __restrict__ w1,   // [NH,3]
    const float* __restrict__ b1,   // [NH]
    const float* __restrict__ w2,   // [1,NH]
    const float* __restrict__ b2,   // [1]
    float* __restrict__ out,
    int Ncols, long long total4)
{
    long long idx4 = (long long)blockIdx.x * blockDim.x + threadIdx.x;
    if (idx4 >= total4) return;

    // Broadcast-load the tiny weight tensors (uniform across warp -> L1 broadcast).
    float w10[NH], w11[NH], w12[NH], bb1[NH], ww2[NH];
#pragma unroll
    for (int h = 0; h < NH; h++) {
        w10[h] = __ldg(&w1[h * 3 + 0]);
        w11[h] = __ldg(&w1[h * 3 + 1]);
        w12[h] = __ldg(&w1[h * 3 + 2]);
        bb1[h] = __ldg(&b1[h]);
        ww2[h] = __ldg(&w2[h]);
    }
    float bb2 = __ldg(&b2[0]);

    long long base = idx4 * 4;                 // element index; 4 consecutive columns, same row
    int m = (int)(base / Ncols);
    int n = (int)(base - (long long)m * Ncols);  // multiple of 4 (Ncols % 4 == 0)

    float pm = __ldg(&post[m]);
    float4 a4 = *reinterpret_cast<const float4*>(A + base);
    float4 p4 = *reinterpret_cast<const float4*>(pre + n);

    // Row-constant part of layer-1 preactivation.
    float c[NH];
#pragma unroll
    for (int h = 0; h < NH; h++) c[h] = fmaf(w12[h], pm, bb1[h]);

    float av[4] = {a4.x, a4.y, a4.z, a4.w};
    float pv[4] = {p4.x, p4.y, p4.z, p4.w};
    float o[4];
#pragma unroll
    for (int j = 0; j < 4; j++) {
        float acc = bb2;
#pragma unroll
        for (int h = 0; h < NH; h++) {
            float z = fmaf(w10[h], av[j], fmaf(w11[h], pv[j], c[h]));
            acc = fmaf(ww2[h], htanh(z), acc);
        }
        o[j] = tanh_acc(acc);
    }
    float4 r = make_float4(o[0], o[1], o[2], o[3]);
    *reinterpret_cast<float4*>(out + base) = r;
}

extern "C" void kernel_launch(void* const* d_in, const int* in_sizes, int n_in,
                              void* d_out, int out_size) {
    const float* A    = (const float*)d_in[0];
    const float* pre  = (const float*)d_in[1];
    const float* post = (const float*)d_in[2];
    const float* w1   = (const float*)d_in[3];
    const float* b1   = (const float*)d_in[4];
    const float* w2   = (const float*)d_in[5];
    const float* b2   = (const float*)d_in[6];
    float* out = (float*)d_out;

    int Ncols = in_sizes[1];                  // 4096
    long long total = (long long)out_size;    // M*N
    long long total4 = total / 4;

    int threads = 256;
    long long blocks = (total4 + threads - 1) / threads;
    synapse_kernel<<<(unsigned)blocks, threads>>>(A, pre, post, w1, b1, w2, b2, out, Ncols, total4);
}

// round 2
// speedup vs baseline: 1.3600x; 1.3600x over previous
#include <cuda_runtime.h>
#include <cuda_bf16.h>

// Synapse_66400194396810: out[m,n] = tanh( w2 . tanh( w1 @ (A[m,n], pre[n], post[m]) + b1 ) + b2 )
// M = N = 4096, Nh = 8.
// R2: weights in __constant__ (no per-thread LDG), 2-D grid (no int64 div),
//     final tanh via tanh.approx (9 MUFU/elem floor).

#define NH 8

// Constant layout: [0..23] w1 (row-major [8][3]), [24..31] b1, [32..39] w2, [40] b2
__constant__ float CW[48];

__device__ __forceinline__ float htanh(float x) {
    float y;
    asm("tanh.approx.f32 %0, %1;" : "=f"(y) : "f"(x));
    return y;
}

__global__ void __launch_bounds__(256) synapse_kernel(
    const float* __restrict__ A,
    const float* __restrict__ pre,
    const float* __restrict__ post,
    float* __restrict__ out,
    int Ncols)
{
    const int m  = blockIdx.y;
    const int n  = (blockIdx.x * blockDim.x + threadIdx.x) * 4;
    if (n >= Ncols) return;
    const int base = m * Ncols + n;   // < 2^24, fits int

    const float pm = post[m];         // block-uniform broadcast
    const float4 a4 = *reinterpret_cast<const float4*>(A + base);
    const float4 p4 = *reinterpret_cast<const float4*>(pre + n);

    // Row-constant part of layer-1 preactivation: c[h] = w1[h][2]*post[m] + b1[h]
    float c[NH];
#pragma unroll
    for (int h = 0; h < NH; h++) c[h] = fmaf(CW[h * 3 + 2], pm, CW[24 + h]);

    const float av[4] = {a4.x, a4.y, a4.z, a4.w};
    const float pv[4] = {p4.x, p4.y, p4.z, p4.w};
    float o[4];
#pragma unroll
    for (int j = 0; j < 4; j++) {
        float acc = CW[40];
#pragma unroll
        for (int h = 0; h < NH; h++) {
            float z = fmaf(CW[h * 3], av[j], fmaf(CW[h * 3 + 1], pv[j], c[h]));
            acc = fmaf(CW[32 + h], htanh(z), acc);
        }
        o[j] = htanh(acc);
    }
    *reinterpret_cast<float4*>(out + base) = make_float4(o[0], o[1], o[2], o[3]);
}

extern "C" void kernel_launch(void* const* d_in, const int* in_sizes, int n_in,
                              void* d_out, int out_size) {
    const float* A    = (const float*)d_in[0];
    const float* pre  = (const float*)d_in[1];
    const float* post = (const float*)d_in[2];
    const float* w1   = (const float*)d_in[3];  // 24 floats
    const float* b1   = (const float*)d_in[4];  // 8
    const float* w2   = (const float*)d_in[5];  // 8
    const float* b2   = (const float*)d_in[6];  // 1
    float* out = (float*)d_out;

    // Stage tiny weights into constant memory (async D2D copies; graph-capturable).
    cudaMemcpyToSymbolAsync(CW, w1,  24 * sizeof(float),  0 * sizeof(float), cudaMemcpyDeviceToDevice);
    cudaMemcpyToSymbolAsync(CW, b1,   8 * sizeof(float), 24 * sizeof(float), cudaMemcpyDeviceToDevice);
    cudaMemcpyToSymbolAsync(CW, w2,   8 * sizeof(float), 32 * sizeof(float), cudaMemcpyDeviceToDevice);
    cudaMemcpyToSymbolAsync(CW, b2,   1 * sizeof(float), 40 * sizeof(float), cudaMemcpyDeviceToDevice);

    const int Ncols = in_sizes[1];              // 4096
    const int M     = out_size / Ncols;         // 4096

    dim3 block(256);
    dim3 grid((Ncols / 4 + 255) / 256, M);      // (4, 4096)
    synapse_kernel<<<grid, block>>>(A, pre, post, out, Ncols);
}

// round 3
// speedup vs baseline: 1.6035x; 1.1791x over previous
#include <cuda_runtime.h>
#include <cuda_bf16.h>

// Synapse_66400194396810: out[m,n] = tanh( w2 . tanh( w1 @ (A[m,n], pre[n], post[m]) + b1 ) + b2 )
// M = N = 4096, Nh = 8. MUFU(tanh)-bound: 9 tanh/elem -> ~34us floor.
// R3: pack-weights kernel replaces 4 memcpy graph nodes (2 nodes total);
//     8 elems/thread; weights stay in __constant__ so ptxas keeps them in URs.

#define NH 8

// Layout: [0..23] w1 (row-major [8][3]), [24..31] b1, [32..39] w2, [40] b2
__constant__ float CW[48];

__device__ __forceinline__ float htanh(float x) {
    float y;
    asm("tanh.approx.f32 %0, %1;" : "=f"(y) : "f"(x));
    return y;
}

// Writes the __constant__ backing store via its global-space alias (cw).
// Ordered before the main kernel by the launch boundary, same as a memcpy node.
__global__ void pack_weights(const float* __restrict__ w1, const float* __restrict__ b1,
                             const float* __restrict__ w2, const float* __restrict__ b2,
                             float* __restrict__ cw) {
    const int i = threadIdx.x;
    if (i < 24)      cw[i] = w1[i];
    else if (i < 32) cw[i] = b1[i - 24];
    else if (i < 40) cw[i] = w2[i - 32];
    else if (i == 40) cw[i] = b2[0];
}

__global__ void __launch_bounds__(256) synapse_kernel(
    const float* __restrict__ A,
    const float* __restrict__ pre,
    const float* __restrict__ post,
    float* __restrict__ out,
    int Ncols)
{
    const int m = blockIdx.y;
    const int n = (blockIdx.x * blockDim.x + threadIdx.x) * 8;
    if (n >= Ncols) return;
    const int base = m * Ncols + n;

    const float pm = post[m];
    const float4 a0 = *reinterpret_cast<const float4*>(A + base);
    const float4 a1 = *reinterpret_cast<const float4*>(A + base + 4);
    const float4 p0 = *reinterpret_cast<const float4*>(pre + n);
    const float4 p1 = *reinterpret_cast<const float4*>(pre + n + 4);

    // Row-constant part of layer-1 preactivation: c[h] = w1[h][2]*post[m] + b1[h]
    float c[NH];
#pragma unroll
    for (int h = 0; h < NH; h++) c[h] = fmaf(CW[h * 3 + 2], pm, CW[24 + h]);

    const float av[8] = {a0.x, a0.y, a0.z, a0.w, a1.x, a1.y, a1.z, a1.w};
    const float pv[8] = {p0.x, p0.y, p0.z, p0.w, p1.x, p1.y, p1.z, p1.w};
    float o[8];
#pragma unroll
    for (int j = 0; j < 8; j++) {
        float acc = CW[40];
#pragma unroll
        for (int h = 0; h < NH; h++) {
            float z = fmaf(CW[h * 3], av[j], fmaf(CW[h * 3 + 1], pv[j], c[h]));
            acc = fmaf(CW[32 + h], htanh(z), acc);
        }
        o[j] = htanh(acc);
    }
    *reinterpret_cast<float4*>(out + base)     = make_float4(o[0], o[1], o[2], o[3]);
    *reinterpret_cast<float4*>(out + base + 4) = make_float4(o[4], o[5], o[6], o[7]);
}

extern "C" void kernel_launch(void* const* d_in, const int* in_sizes, int n_in,
                              void* d_out, int out_size) {
    const float* A    = (const float*)d_in[0];
    const float* pre  = (const float*)d_in[1];
    const float* post = (const float*)d_in[2];
    const float* w1   = (const float*)d_in[3];
    const float* b1   = (const float*)d_in[4];
    const float* w2   = (const float*)d_in[5];
    const float* b2   = (const float*)d_in[6];
    float* out = (float*)d_out;

    void* cw_alias = nullptr;
    cudaGetSymbolAddress(&cw_alias, CW);  // host-side query; capture-safe

    pack_weights<<<1, 64>>>(w1, b1, w2, b2, (float*)cw_alias);

    const int Ncols = in_sizes[1];        // 4096
    const int M     = out_size / Ncols;   // 4096

    dim3 block(256);
    dim3 grid((Ncols / 8 + 255) / 256, M);  // (2, 4096)
    synapse_kernel<<<grid, block>>>(A, pre, post, out, Ncols);
}